// round 3
// baseline (speedup 1.0000x reference)
#include <cuda_runtime.h>
#include <cuda_bf16.h>
#include <cstdint>

// Problem constants
#define N_ROWS      8192
#define NUM_CLASSES 32000
#define VEC_PER_ROW (NUM_CLASSES / 4)   // 8000 float4
#define TAU         0.05f
#define THREADS     256

// Device-global scratch (no cudaMalloc allowed).
// g_loss_sum starts 0 at module load; the last block of every launch resets
// it to 0 after use, so every graph replay sees a clean accumulator.
__device__ double       g_loss_sum = 0.0;
__device__ unsigned int g_done     = 0;   // atomicInc auto-wraps to 0

// Per-element math:
//   t  = 0.5*x - tau ; tp = max(t,0) ; p = tp^2
//   sum_j [ (p - p^1.5)/0.75 + p*(x - 2tau) ] = (2/3) * sum_j tp^2*(tp+2)
// Row loss = (2/3) * sum - (x[target] - 2*tau)
__global__ __launch_bounds__(THREADS, 8)
void relu15_fused_kernel(const float* __restrict__ X,
                         const int* __restrict__ target,
                         float* __restrict__ out) {
    const int row = blockIdx.x;
    const float4* __restrict__ xr =
        reinterpret_cast<const float4*>(X + (size_t)row * NUM_CLASSES);

    float acc = 0.0f;

    // 8000 float4 per row, 256 threads -> 31.25 vec4/thread.
    int i = threadIdx.x;
    #pragma unroll 8
    for (; i < VEC_PER_ROW; i += THREADS) {
        float4 v = __ldg(xr + i);

        float t0 = fmaxf(fmaf(0.5f, v.x, -TAU), 0.0f);
        float t1 = fmaxf(fmaf(0.5f, v.y, -TAU), 0.0f);
        float t2 = fmaxf(fmaf(0.5f, v.z, -TAU), 0.0f);
        float t3 = fmaxf(fmaf(0.5f, v.w, -TAU), 0.0f);

        acc = fmaf(t0 * t0, t0 + 2.0f, acc);
        acc = fmaf(t1 * t1, t1 + 2.0f, acc);
        acc = fmaf(t2 * t2, t2 + 2.0f, acc);
        acc = fmaf(t3 * t3, t3 + 2.0f, acc);
    }

    // Warp reduce
    #pragma unroll
    for (int off = 16; off > 0; off >>= 1)
        acc += __shfl_down_sync(0xFFFFFFFFu, acc, off);

    __shared__ float warp_sums[THREADS / 32];
    const int lane = threadIdx.x & 31;
    const int wid  = threadIdx.x >> 5;
    if (lane == 0) warp_sums[wid] = acc;
    __syncthreads();

    if (wid == 0) {
        float s = (lane < THREADS / 32) ? warp_sums[lane] : 0.0f;
        #pragma unroll
        for (int off = 4; off > 0; off >>= 1)
            s += __shfl_down_sync(0xFFFFFFFFu, s, off);

        if (lane == 0) {
            int tgt = target[row];
            tgt = min(max(tgt, 0), NUM_CLASSES - 1);   // defensive clamp
            float xt = __ldg(X + (size_t)row * NUM_CLASSES + (size_t)tgt);
            float row_loss = (2.0f / 3.0f) * s - (xt - 2.0f * TAU);

            atomicAdd(&g_loss_sum, (double)row_loss);
            __threadfence();

            // Completion counter: atomicInc wraps back to 0 at N_ROWS-1,
            // so the counter is automatically reset for the next replay.
            unsigned int prev = atomicInc(&g_done, N_ROWS - 1);
            if (prev == N_ROWS - 1) {
                __threadfence();
                double total = g_loss_sum;
                out[0] = (float)(total / (double)N_ROWS);
                g_loss_sum = 0.0;          // reset for next graph replay
                __threadfence();
            }
        }
    }
}

extern "C" void kernel_launch(void* const* d_in, const int* in_sizes, int n_in,
                              void* d_out, int out_size) {
    const float* X      = (const float*)d_in[0];
    const int*   target = (const int*)d_in[1];
    float*       out    = (float*)d_out;

    relu15_fused_kernel<<<N_ROWS, THREADS>>>(X, target, out);
}

// round 4
// speedup vs baseline: 1.0117x; 1.0117x over previous
#include <cuda_runtime.h>
#include <cuda_bf16.h>
#include <cstdint>

// Problem constants
#define N_ROWS      8192
#define NUM_CLASSES 32000
#define VEC_PER_ROW (NUM_CLASSES / 4)   // 8000 float4
#define TAU         0.05f
#define THREADS     256

// Device-global scratch (no cudaMalloc allowed).
// g_loss_sum starts 0 at module load; the last block of every launch resets
// it to 0 after use, so every graph replay sees a clean accumulator.
__device__ double       g_loss_sum = 0.0;
__device__ unsigned int g_done     = 0;   // atomicInc auto-wraps to 0

// Per-element math:
//   t  = 0.5*x - tau ; tp = max(t,0) ; p = tp^2
//   sum_j [ (p - p^1.5)/0.75 + p*(x - 2tau) ] = (2/3) * sum_j tp^2*(tp+2)
// Row loss = (2/3) * sum - (x[target] - 2*tau)
__global__ __launch_bounds__(THREADS, 8)
void relu15_fused_kernel(const float* __restrict__ X,
                         const int* __restrict__ target,
                         float* __restrict__ out) {
    const int row = blockIdx.x;
    const float4* __restrict__ xr =
        reinterpret_cast<const float4*>(X + (size_t)row * NUM_CLASSES);

    float acc = 0.0f;

    // 8000 float4 per row, 256 threads -> 31.25 vec4/thread.
    // unroll 4 restores the R2 mainloop shape (measured 7.3 TB/s).
    // __ldcs: single-touch stream, evict-first in L2.
    int i = threadIdx.x;
    #pragma unroll 4
    for (; i < VEC_PER_ROW; i += THREADS) {
        float4 v = __ldcs(xr + i);

        float t0 = fmaxf(fmaf(0.5f, v.x, -TAU), 0.0f);
        float t1 = fmaxf(fmaf(0.5f, v.y, -TAU), 0.0f);
        float t2 = fmaxf(fmaf(0.5f, v.z, -TAU), 0.0f);
        float t3 = fmaxf(fmaf(0.5f, v.w, -TAU), 0.0f);

        acc = fmaf(t0 * t0, t0 + 2.0f, acc);
        acc = fmaf(t1 * t1, t1 + 2.0f, acc);
        acc = fmaf(t2 * t2, t2 + 2.0f, acc);
        acc = fmaf(t3 * t3, t3 + 2.0f, acc);
    }

    // Warp reduce
    #pragma unroll
    for (int off = 16; off > 0; off >>= 1)
        acc += __shfl_down_sync(0xFFFFFFFFu, acc, off);

    __shared__ float warp_sums[THREADS / 32];
    const int lane = threadIdx.x & 31;
    const int wid  = threadIdx.x >> 5;
    if (lane == 0) warp_sums[wid] = acc;
    __syncthreads();

    if (wid == 0) {
        float s = (lane < THREADS / 32) ? warp_sums[lane] : 0.0f;
        #pragma unroll
        for (int off = 4; off > 0; off >>= 1)
            s += __shfl_down_sync(0xFFFFFFFFu, s, off);

        if (lane == 0) {
            int tgt = target[row];
            tgt = min(max(tgt, 0), NUM_CLASSES - 1);   // defensive clamp
            float xt = __ldg(X + (size_t)row * NUM_CLASSES + (size_t)tgt);
            float row_loss = (2.0f / 3.0f) * s - (xt - 2.0f * TAU);

            atomicAdd(&g_loss_sum, (double)row_loss);
            __threadfence();

            // Completion counter: atomicInc wraps back to 0 at N_ROWS-1,
            // so the counter is automatically reset for the next replay.
            unsigned int prev = atomicInc(&g_done, N_ROWS - 1);
            if (prev == N_ROWS - 1) {
                __threadfence();
                double total = g_loss_sum;
                out[0] = (float)(total / (double)N_ROWS);
                g_loss_sum = 0.0;          // reset for next graph replay
                __threadfence();
            }
        }
    }
}

extern "C" void kernel_launch(void* const* d_in, const int* in_sizes, int n_in,
                              void* d_out, int out_size) {
    const float* X      = (const float*)d_in[0];
    const int*   target = (const int*)d_in[1];
    float*       out    = (float*)d_out;

    relu15_fused_kernel<<<N_ROWS, THREADS>>>(X, target, out);
}